// round 3
// baseline (speedup 1.0000x reference)
#include <cuda_runtime.h>
#include <cuda_bf16.h>

#define N_ATOMS 50000
#define N_BONDS 100000
#define NE      (2 * N_BONDS)       // 200000 directed edges
#define HIDDEN  300
#define ATOM_DIM 133
#define BOND_DIM 14
#define N_MOL   2048
#define FEAT_DIM 200
#define DEPTH   3
#define OUT_COLS (HIDDEN + FEAT_DIM)  // 500

// ---------------- scratch (device globals; no allocation allowed) ----------
__device__ float g_h0 [(size_t)NE * HIDDEN];        // 240 MB
__device__ float g_hA [(size_t)NE * HIDDEN];        // 240 MB
__device__ float g_hB [(size_t)NE * HIDDEN];        // 240 MB
__device__ float g_inc[(size_t)N_ATOMS * HIDDEN];   // 60 MB (also reused as m_v)

// packed dual-FMA: d.lo += a.lo*b.lo ; d.hi += a.hi*b.hi  (Blackwell f32x2 pipe)
__device__ __forceinline__ void ffma2(unsigned long long& d,
                                      unsigned long long a,
                                      unsigned long long b)
{
    asm("fma.rn.f32x2 %0, %1, %2, %0;" : "+l"(d) : "l"(a), "l"(b));
}

// ---------------------------------------------------------------------------
// Fused GEMM:  out[r, 0:300] = relu( A(r,:) @ W + bias (+ resid[r,:]) )
// A assembled on the fly:
//   mode 0: A(r,k) = k<14  ? edge_attr[r*14+k] : x[src[r]*133 + k-14]   (K=147)
//   mode 2: A(r,k) = k<133 ? x[r*133+k]        : m_v[r*300 + k-133]     (K=433)
//   mode 3: A(r,k) = inc[src[r]*300+k] - h[rev[r]*300+k]                (K=300)
// BM=128, BN=64, BK=16, 128 threads, 8x8 microtile via fma.rn.f32x2.
// A tile kept DUPLICATED in smem so packed broadcast operands load directly.
// ---------------------------------------------------------------------------
#define A_STRIDE 260   // floats per k-row of duplicated A tile (256 data + 4 pad)
#define B_STRIDE 68    // floats per k-row of B tile (64 data + 4 pad)

__global__ __launch_bounds__(128, 4)
void gemm_fused(int mode, int rows, int K,
                const float* __restrict__ G0,   // m0: edge_attr | m2: x   | m3: inc
                const float* __restrict__ G1,   // m0: x         | m2: m_v | m3: h
                const int*   __restrict__ gidx, // m0: src       | m3: src
                const int*   __restrict__ gidx2,// m3: rev
                const float* __restrict__ W,    // [K, 300]
                const float* __restrict__ bias, // [300]
                const float* __restrict__ resid,// [rows, 300] or null
                float* __restrict__ out)        // [rows, 300]
{
    __shared__ float Asd[16 * A_STRIDE];  // duplicated: Asd[k][2m],Asd[k][2m+1] = A(m,k)
    __shared__ float Bs [16 * B_STRIDE];

    const int tid = threadIdx.x;
    const int m0 = blockIdx.x * 128;
    const int n0 = blockIdx.y * 64;
    const int ty = tid >> 3;       // 0..15 -> rows ty*8..+7
    const int tx = tid & 7;        // 0..7  -> cols tx*8..+7

    unsigned long long acc[8][4];
#pragma unroll
    for (int i = 0; i < 8; i++)
#pragma unroll
        for (int j = 0; j < 4; j++) acc[i][j] = 0ULL;

    const int ksteps = (K + 15) / 16;
    for (int ks = 0; ks < ksteps; ks++) {
        const int k0 = ks * 16;
        // ---- stage A tile: 128 rows x 16 k, duplicated write
#pragma unroll
        for (int i = 0; i < 16; i++) {
            int li = tid + i * 128;
            int r  = li >> 4;          // 0..127
            int k  = li & 15;
            int row = m0 + r;
            int kg  = k0 + k;
            float v = 0.f;
            if (row < rows && kg < K) {
                if (mode == 3) {
                    int s  = gidx[row];
                    int rv = gidx2[row];
                    v = G0[(size_t)s  * HIDDEN + kg]
                      - G1[(size_t)rv * HIDDEN + kg];
                } else if (mode == 0) {
                    if (kg < BOND_DIM) v = G0[row * BOND_DIM + kg];
                    else {
                        int s = gidx[row];
                        v = G1[(size_t)s * ATOM_DIM + (kg - BOND_DIM)];
                    }
                } else { // mode 2
                    if (kg < ATOM_DIM) v = G0[(size_t)row * ATOM_DIM + kg];
                    else               v = G1[(size_t)row * HIDDEN + (kg - ATOM_DIM)];
                }
            }
            *(float2*)&Asd[k * A_STRIDE + 2 * r] = make_float2(v, v);
        }
        // ---- stage B tile: 16 k x 64 n, n contiguous
#pragma unroll
        for (int i = 0; i < 8; i++) {
            int li = tid + i * 128;
            int k  = li >> 6;          // 0..15
            int n  = li & 63;
            int kg = k0 + k;
            int ng = n0 + n;
            float v = 0.f;
            if (kg < K && ng < HIDDEN) v = W[(size_t)kg * HIDDEN + ng];
            Bs[k * B_STRIDE + n] = v;
        }
        __syncthreads();

#pragma unroll
        for (int kk = 0; kk < 16; kk++) {
            const float* arow = &Asd[kk * A_STRIDE + ty * 16];
            ulonglong2 a01 = *(const ulonglong2*)(arow + 0);   // dup(a0),dup(a1)
            ulonglong2 a23 = *(const ulonglong2*)(arow + 4);
            ulonglong2 a45 = *(const ulonglong2*)(arow + 8);
            ulonglong2 a67 = *(const ulonglong2*)(arow + 12);
            const float* brow = &Bs[kk * B_STRIDE + tx * 8];
            ulonglong2 b03 = *(const ulonglong2*)(brow + 0);   // (b0,b1),(b2,b3)
            ulonglong2 b47 = *(const ulonglong2*)(brow + 4);

            unsigned long long ad[8] = { a01.x, a01.y, a23.x, a23.y,
                                         a45.x, a45.y, a67.x, a67.y };
#pragma unroll
            for (int i = 0; i < 8; i++) {
                ffma2(acc[i][0], ad[i], b03.x);
                ffma2(acc[i][1], ad[i], b03.y);
                ffma2(acc[i][2], ad[i], b47.x);
                ffma2(acc[i][3], ad[i], b47.y);
            }
        }
        __syncthreads();
    }

    // ---- epilogue: bias (+resid) + relu
#pragma unroll
    for (int i = 0; i < 8; i++) {
        int row = m0 + ty * 8 + i;
        if (row >= rows) continue;
#pragma unroll
        for (int jp = 0; jp < 4; jp++) {
            union { unsigned long long u; float2 f; } c;
            c.u = acc[i][jp];
            int col = n0 + tx * 8 + jp * 2;
            if (col < HIDDEN) {
                float v = c.f.x + bias[col];
                if (resid) v += resid[(size_t)row * HIDDEN + col];
                out[(size_t)row * HIDDEN + col] = v > 0.f ? v : 0.f;
            }
            if (col + 1 < HIDDEN) {
                float v = c.f.y + bias[col + 1];
                if (resid) v += resid[(size_t)row * HIDDEN + col + 1];
                out[(size_t)row * HIDDEN + col + 1] = v > 0.f ? v : 0.f;
            }
        }
    }
}

// ---------------------------------------------------------------------------
// Segment sum: acc[idx[e], :] += h[e, :]    (acc pre-zeroed)
// ---------------------------------------------------------------------------
__global__ void scatter_add(const float* __restrict__ h,
                            const int*   __restrict__ idx,
                            float* __restrict__ acc, int rows)
{
    int gid = blockIdx.x * blockDim.x + threadIdx.x;
    if (gid >= rows * 75) return;
    int e = gid / 75;
    int q = gid % 75;
    float4 v = ((const float4*)h)[(size_t)e * 75 + q];
    int d = idx[e];
    float* p = acc + (size_t)d * HIDDEN + q * 4;
    atomicAdd(p + 0, v.x);
    atomicAdd(p + 1, v.y);
    atomicAdd(p + 2, v.z);
    atomicAdd(p + 3, v.w);
}

// out[mol, 0:300] = 0 ; out[mol, 300:500] = features[mol, :]
__global__ void init_out(float* __restrict__ out, const float* __restrict__ feat)
{
    int gid = blockIdx.x * blockDim.x + threadIdx.x;
    if (gid >= N_MOL * OUT_COLS) return;
    int mol = gid / OUT_COLS;
    int c   = gid % OUT_COLS;
    out[gid] = (c < HIDDEN) ? 0.f : feat[mol * FEAT_DIM + (c - HIDDEN)];
}

// out[mol_id[v], j] += h_v[v, j]
__global__ void readout(const float* __restrict__ hv,
                        const int* __restrict__ mol_id,
                        float* __restrict__ out)
{
    int gid = blockIdx.x * blockDim.x + threadIdx.x;
    if (gid >= N_ATOMS * 75) return;
    int v = gid / 75;
    int q = gid % 75;
    float4 x = ((const float4*)hv)[(size_t)v * 75 + q];
    int mol = mol_id[v];
    float* p = out + (size_t)mol * OUT_COLS + q * 4;
    atomicAdd(p + 0, x.x);
    atomicAdd(p + 1, x.y);
    atomicAdd(p + 2, x.z);
    atomicAdd(p + 3, x.w);
}

// ---------------------------------------------------------------------------
extern "C" void kernel_launch(void* const* d_in, const int* in_sizes, int n_in,
                              void* d_out, int out_size)
{
    const float* x         = (const float*)d_in[0];
    const float* edge_attr = (const float*)d_in[1];
    const int*   edge_src  = (const int*)  d_in[2];
    const int*   edge_dst  = (const int*)  d_in[3];
    const int*   b2rev     = (const int*)  d_in[4];
    const int*   mol_id    = (const int*)  d_in[5];
    const float* features  = (const float*)d_in[6];
    const float* Wi        = (const float*)d_in[7];
    const float* bi        = (const float*)d_in[8];
    const float* Wm        = (const float*)d_in[9];
    const float* bm        = (const float*)d_in[10];
    const float* Wa        = (const float*)d_in[11];
    const float* ba        = (const float*)d_in[12];
    float* out = (float*)d_out;

    float *h0, *hA, *hB, *inc;
    cudaGetSymbolAddress((void**)&h0,  g_h0);
    cudaGetSymbolAddress((void**)&hA,  g_hA);
    cudaGetSymbolAddress((void**)&hB,  g_hB);
    cudaGetSymbolAddress((void**)&inc, g_inc);

    dim3 blk(128);
    dim3 gemm_grid_E((NE + 127) / 128, (HIDDEN + 63) / 64);
    dim3 gemm_grid_V((N_ATOMS + 127) / 128, (HIDDEN + 63) / 64);
    dim3 sblk(256);
    int scatE = (NE * 75 + 255) / 256;
    int scatV = (N_ATOMS * 75 + 255) / 256;

    // h0 = relu([edge_attr, x[src]] @ Wi + bi)
    gemm_fused<<<gemm_grid_E, blk>>>(0, NE, BOND_DIM + ATOM_DIM,
                                     edge_attr, x, edge_src, nullptr,
                                     Wi, bi, nullptr, h0);

    const float* hin = h0;
    float* houts[3] = { hA, hB, hA };
    for (int it = 0; it < DEPTH; it++) {
        float* hout = houts[it];
        cudaMemsetAsync(inc, 0, (size_t)N_ATOMS * HIDDEN * sizeof(float));
        scatter_add<<<scatE, sblk>>>(hin, edge_dst, inc, NE);
        // h = relu(h0 + (inc[src] - h[rev]) @ Wm + bm), A assembled in-kernel
        gemm_fused<<<gemm_grid_E, blk>>>(3, NE, HIDDEN,
                                         inc, hin, edge_src, b2rev,
                                         Wm, bm, h0, hout);
        hin = hout;
    }

    // m_v = segment_sum(h over edge_src) — reuse inc buffer
    cudaMemsetAsync(inc, 0, (size_t)N_ATOMS * HIDDEN * sizeof(float));
    scatter_add<<<scatE, sblk>>>(hin, edge_src, inc, NE);

    // h_v = relu([x, m_v] @ Wa + ba) -> reuse hB
    gemm_fused<<<gemm_grid_V, blk>>>(2, N_ATOMS, ATOM_DIM + HIDDEN,
                                     x, inc, nullptr, nullptr,
                                     Wa, ba, nullptr, hB);

    // output: zeros | features, then molecule-sum readout
    init_out<<<(N_MOL * OUT_COLS + 255) / 256, sblk>>>(out, features);
    readout<<<scatV, sblk>>>(hB, mol_id, out);
}

// round 6
// speedup vs baseline: 1.4738x; 1.4738x over previous
#include <cuda_runtime.h>
#include <cuda_bf16.h>

#define N_ATOMS 50000
#define N_BONDS 100000
#define NE      (2 * N_BONDS)       // 200000 directed edges
#define HIDDEN  300
#define ATOM_DIM 133
#define BOND_DIM 14
#define N_MOL   2048
#define FEAT_DIM 200
#define DEPTH   3
#define OUT_COLS (HIDDEN + FEAT_DIM)  // 500

// ---------------- scratch (device globals; no allocation allowed) ----------
__device__ float g_h0 [(size_t)NE * HIDDEN];        // 240 MB
__device__ float g_hA [(size_t)NE * HIDDEN];        // 240 MB
__device__ float g_hB [(size_t)NE * HIDDEN];        // 240 MB
__device__ float g_inc[(size_t)N_ATOMS * HIDDEN];   // 60 MB (also reused as m_v)

// ---------------------------------------------------------------------------
// Fused GEMM:  out[r, 0:300] = relu( A(r,:) @ W + bias (+ resid[r,:]) )
//   mode 0: A(r,k) = k<14  ? edge_attr[r*14+k] : x[src[r]*133 + k-14]   (K=147)
//   mode 2: A(r,k) = k<133 ? x[r*133+k]        : m_v[r*300 + k-133]     (K=433)
//   mode 3: A(r,k) = inc[src[r]*300+k] - h[rev[r]*300+k]                (K=300)
// BM=128, BN=64, BK=16, 256 threads, 8x4 microtile, scalar fmaf.
// A tile stored [k][m]-major in smem: a-loads are 2x LDS.128 per kk.
// ---------------------------------------------------------------------------
#define A_STRIDE 132   // floats per k-row of A tile (128 data + 4 pad)
#define B_STRIDE 68    // floats per k-row of B tile (64 data + 4 pad)

__global__ __launch_bounds__(256)
void gemm_fused(int mode, int rows, int K,
                const float* __restrict__ G0,   // m0: edge_attr | m2: x   | m3: inc
                const float* __restrict__ G1,   // m0: x         | m2: m_v | m3: h
                const int*   __restrict__ gidx, // m0: src       | m3: src
                const int*   __restrict__ gidx2,// m3: rev
                const float* __restrict__ W,    // [K, 300]
                const float* __restrict__ bias, // [300]
                const float* __restrict__ resid,// [rows, 300] or null
                float* __restrict__ out)        // [rows, 300]
{
    __shared__ float As[16 * A_STRIDE];   // As[k*A_STRIDE + m] = A(m0+m, k0+k)
    __shared__ float Bs[16 * B_STRIDE];   // Bs[k*B_STRIDE + n] = W(k0+k, n0+n)

    const int tid = threadIdx.x;
    const int m0 = blockIdx.x * 128;
    const int n0 = blockIdx.y * 64;
    const int ty = tid >> 4;       // 0..15 -> rows ty*8 .. +7
    const int tx = tid & 15;       // 0..15 -> cols tx*4 .. +3

    float acc[8][4];
#pragma unroll
    for (int i = 0; i < 8; i++)
#pragma unroll
        for (int j = 0; j < 4; j++) acc[i][j] = 0.f;

    const int ksteps = (K + 15) / 16;
    for (int ks = 0; ks < ksteps; ks++) {
        const int k0 = ks * 16;
        const bool kfull = (k0 + 16 <= K);

        // ---- stage A tile (128 rows x 16 k) into [k][m] layout
        if (mode == 3 && kfull) {
            // vectorized: 512 float4 loads (2/thread); rows 300-float aligned
#pragma unroll
            for (int i = 0; i < 2; i++) {
                int li = tid + i * 256;      // 0..511
                int r  = li >> 2;            // 0..127
                int k4 = (li & 3) * 4;       // 0,4,8,12
                int row = m0 + r;
                float4 v = make_float4(0.f, 0.f, 0.f, 0.f);
                if (row < rows) {
                    int s  = gidx[row];
                    int rv = gidx2[row];
                    float4 p = *(const float4*)&G0[(size_t)s  * HIDDEN + k0 + k4];
                    float4 q = *(const float4*)&G1[(size_t)rv * HIDDEN + k0 + k4];
                    v.x = p.x - q.x; v.y = p.y - q.y;
                    v.z = p.z - q.z; v.w = p.w - q.w;
                }
                As[(k4 + 0) * A_STRIDE + r] = v.x;
                As[(k4 + 1) * A_STRIDE + r] = v.y;
                As[(k4 + 2) * A_STRIDE + r] = v.z;
                As[(k4 + 3) * A_STRIDE + r] = v.w;
            }
        } else {
            // generic scalar path (k contiguous per thread-group for coalescing)
#pragma unroll
            for (int i = 0; i < 8; i++) {
                int li = tid + i * 256;
                int r  = li >> 4;          // 0..127
                int k  = li & 15;
                int row = m0 + r;
                int kg  = k0 + k;
                float v = 0.f;
                if (row < rows && kg < K) {
                    if (mode == 3) {
                        int s  = gidx[row];
                        int rv = gidx2[row];
                        v = G0[(size_t)s  * HIDDEN + kg]
                          - G1[(size_t)rv * HIDDEN + kg];
                    } else if (mode == 0) {
                        if (kg < BOND_DIM) v = G0[row * BOND_DIM + kg];
                        else {
                            int s = gidx[row];
                            v = G1[(size_t)s * ATOM_DIM + (kg - BOND_DIM)];
                        }
                    } else { // mode 2
                        if (kg < ATOM_DIM) v = G0[(size_t)row * ATOM_DIM + kg];
                        else               v = G1[(size_t)row * HIDDEN + (kg - ATOM_DIM)];
                    }
                }
                As[k * A_STRIDE + r] = v;
            }
        }

        // ---- stage B tile (16 k x 64 n): 256 float4s, one per thread
        {
            int k  = tid >> 4;             // 0..15
            int n4 = (tid & 15) * 4;       // 0..60
            int kg = k0 + k;
            int ng = n0 + n4;
            float4 v = make_float4(0.f, 0.f, 0.f, 0.f);
            if (kg < K && ng < HIDDEN) {   // HIDDEN % 4 == 0 -> full float4 ok
                v = *(const float4*)&W[(size_t)kg * HIDDEN + ng];
            }
            *(float4*)&Bs[k * B_STRIDE + n4] = v;
        }
        __syncthreads();

#pragma unroll
        for (int kk = 0; kk < 16; kk++) {
            const float* arow = &As[kk * A_STRIDE + ty * 8];
            float4 a0 = *(const float4*)(arow + 0);
            float4 a1 = *(const float4*)(arow + 4);
            float4 b  = *(const float4*)&Bs[kk * B_STRIDE + tx * 4];
            float a[8] = { a0.x, a0.y, a0.z, a0.w, a1.x, a1.y, a1.z, a1.w };
#pragma unroll
            for (int i = 0; i < 8; i++) {
                acc[i][0] = fmaf(a[i], b.x, acc[i][0]);
                acc[i][1] = fmaf(a[i], b.y, acc[i][1]);
                acc[i][2] = fmaf(a[i], b.z, acc[i][2]);
                acc[i][3] = fmaf(a[i], b.w, acc[i][3]);
            }
        }
        __syncthreads();
    }

    // ---- epilogue: bias (+resid) + relu, float4 stores
    int col = n0 + tx * 4;
    if (col < HIDDEN) {                    // HIDDEN % 4 == 0 -> full float4
        float4 bv = *(const float4*)&bias[col];
#pragma unroll
        for (int i = 0; i < 8; i++) {
            int row = m0 + ty * 8 + i;
            if (row >= rows) continue;
            float4 v;
            v.x = acc[i][0] + bv.x;
            v.y = acc[i][1] + bv.y;
            v.z = acc[i][2] + bv.z;
            v.w = acc[i][3] + bv.w;
            if (resid) {
                float4 rz = *(const float4*)&resid[(size_t)row * HIDDEN + col];
                v.x += rz.x; v.y += rz.y; v.z += rz.z; v.w += rz.w;
            }
            v.x = v.x > 0.f ? v.x : 0.f;
            v.y = v.y > 0.f ? v.y : 0.f;
            v.z = v.z > 0.f ? v.z : 0.f;
            v.w = v.w > 0.f ? v.w : 0.f;
            *(float4*)&out[(size_t)row * HIDDEN + col] = v;
        }
    }
}

// ---------------------------------------------------------------------------
// Segment sum: acc[idx[e], :] += h[e, :]    (acc pre-zeroed)
// ---------------------------------------------------------------------------
__global__ void scatter_add(const float* __restrict__ h,
                            const int*   __restrict__ idx,
                            float* __restrict__ acc, int rows)
{
    int gid = blockIdx.x * blockDim.x + threadIdx.x;
    if (gid >= rows * 75) return;
    int e = gid / 75;
    int q = gid % 75;
    float4 v = ((const float4*)h)[(size_t)e * 75 + q];
    int d = idx[e];
    float* p = acc + (size_t)d * HIDDEN + q * 4;
    atomicAdd(p + 0, v.x);
    atomicAdd(p + 1, v.y);
    atomicAdd(p + 2, v.z);
    atomicAdd(p + 3, v.w);
}

// out[mol, 0:300] = 0 ; out[mol, 300:500] = features[mol, :]
__global__ void init_out(float* __restrict__ out, const float* __restrict__ feat)
{
    int gid = blockIdx.x * blockDim.x + threadIdx.x;
    if (gid >= N_MOL * OUT_COLS) return;
    int mol = gid / OUT_COLS;
    int c   = gid % OUT_COLS;
    out[gid] = (c < HIDDEN) ? 0.f : feat[mol * FEAT_DIM + (c - HIDDEN)];
}

// out[mol_id[v], j] += h_v[v, j]
__global__ void readout(const float* __restrict__ hv,
                        const int* __restrict__ mol_id,
                        float* __restrict__ out)
{
    int gid = blockIdx.x * blockDim.x + threadIdx.x;
    if (gid >= N_ATOMS * 75) return;
    int v = gid / 75;
    int q = gid % 75;
    float4 x = ((const float4*)hv)[(size_t)v * 75 + q];
    int mol = mol_id[v];
    float* p = out + (size_t)mol * OUT_COLS + q * 4;
    atomicAdd(p + 0, x.x);
    atomicAdd(p + 1, x.y);
    atomicAdd(p + 2, x.z);
    atomicAdd(p + 3, x.w);
}

// ---------------------------------------------------------------------------
extern "C" void kernel_launch(void* const* d_in, const int* in_sizes, int n_in,
                              void* d_out, int out_size)
{
    const float* x         = (const float*)d_in[0];
    const float* edge_attr = (const float*)d_in[1];
    const int*   edge_src  = (const int*)  d_in[2];
    const int*   edge_dst  = (const int*)  d_in[3];
    const int*   b2rev     = (const int*)  d_in[4];
    const int*   mol_id    = (const int*)  d_in[5];
    const float* features  = (const float*)d_in[6];
    const float* Wi        = (const float*)d_in[7];
    const float* bi        = (const float*)d_in[8];
    const float* Wm        = (const float*)d_in[9];
    const float* bm        = (const float*)d_in[10];
    const float* Wa        = (const float*)d_in[11];
    const float* ba        = (const float*)d_in[12];
    float* out = (float*)d_out;

    float *h0, *hA, *hB, *inc;
    cudaGetSymbolAddress((void**)&h0,  g_h0);
    cudaGetSymbolAddress((void**)&hA,  g_hA);
    cudaGetSymbolAddress((void**)&hB,  g_hB);
    cudaGetSymbolAddress((void**)&inc, g_inc);

    dim3 blk(256);
    dim3 gemm_grid_E((NE + 127) / 128, (HIDDEN + 63) / 64);
    dim3 gemm_grid_V((N_ATOMS + 127) / 128, (HIDDEN + 63) / 64);
    dim3 sblk(256);
    int scatE = (NE * 75 + 255) / 256;
    int scatV = (N_ATOMS * 75 + 255) / 256;

    // h0 = relu([edge_attr, x[src]] @ Wi + bi)
    gemm_fused<<<gemm_grid_E, blk>>>(0, NE, BOND_DIM + ATOM_DIM,
                                     edge_attr, x, edge_src, nullptr,
                                     Wi, bi, nullptr, h0);

    const float* hin = h0;
    float* houts[3] = { hA, hB, hA };
    for (int it = 0; it < DEPTH; it++) {
        float* hout = houts[it];
        cudaMemsetAsync(inc, 0, (size_t)N_ATOMS * HIDDEN * sizeof(float));
        scatter_add<<<scatE, sblk>>>(hin, edge_dst, inc, NE);
        // h = relu(h0 + (inc[src] - h[rev]) @ Wm + bm), A assembled in-kernel
        gemm_fused<<<gemm_grid_E, blk>>>(3, NE, HIDDEN,
                                         inc, hin, edge_src, b2rev,
                                         Wm, bm, h0, hout);
        hin = hout;
    }

    // m_v = segment_sum(h over edge_src) — reuse inc buffer
    cudaMemsetAsync(inc, 0, (size_t)N_ATOMS * HIDDEN * sizeof(float));
    scatter_add<<<scatE, sblk>>>(hin, edge_src, inc, NE);

    // h_v = relu([x, m_v] @ Wa + ba) -> reuse hB
    gemm_fused<<<gemm_grid_V, blk>>>(2, N_ATOMS, ATOM_DIM + HIDDEN,
                                     x, inc, nullptr, nullptr,
                                     Wa, ba, nullptr, hB);

    // output: zeros | features, then molecule-sum readout
    init_out<<<(N_MOL * OUT_COLS + 255) / 256, sblk>>>(out, features);
    readout<<<scatV, sblk>>>(hB, mol_id, out);
}

// round 8
// speedup vs baseline: 2.4990x; 1.6956x over previous
#include <cuda_runtime.h>
#include <cuda_bf16.h>
#include <cstdint>

#define N_ATOMS 50000
#define N_BONDS 100000
#define NE      (2 * N_BONDS)       // 200000 directed edges
#define HIDDEN  300
#define ATOM_DIM 133
#define BOND_DIM 14
#define N_MOL   2048
#define FEAT_DIM 200
#define DEPTH   3
#define OUT_COLS (HIDDEN + FEAT_DIM)  // 500

#define NPAD    320                 // padded N (2 x 160)
#define KPAD_I  192                 // mode 0: K=147
#define KPAD_M  320                 // mode 3: K=300
#define KPAD_A  448                 // mode 2: K=433

// ---------------- scratch (device globals; no allocation allowed) ----------
__device__ float g_h0 [(size_t)NE * HIDDEN];
__device__ float g_hA [(size_t)NE * HIDDEN];
__device__ float g_hB [(size_t)NE * HIDDEN];
__device__ float g_inc[(size_t)N_ATOMS * HIDDEN];
// pre-split weights, layout [NPAD][Kpad] bf16 (B[n][k] = W[k][n]), zero-padded
__device__ __nv_bfloat16 g_Wi_hi[NPAD * KPAD_I];
__device__ __nv_bfloat16 g_Wi_lo[NPAD * KPAD_I];
__device__ __nv_bfloat16 g_Wm_hi[NPAD * KPAD_M];
__device__ __nv_bfloat16 g_Wm_lo[NPAD * KPAD_M];
__device__ __nv_bfloat16 g_Wa_hi[NPAD * KPAD_A];
__device__ __nv_bfloat16 g_Wa_lo[NPAD * KPAD_A];

// ============================ PTX helpers (sm_80+) ==========================
__device__ __forceinline__ uint32_t smem_u32(const void* p) {
    uint32_t a;
    asm("{ .reg .u64 t; cvta.to.shared.u64 t, %1; cvt.u32.u64 %0, t; }"
        : "=r"(a) : "l"(p));
    return a;
}
__device__ __forceinline__ void ldm_x4(uint32_t* r, uint32_t addr) {
    asm volatile("ldmatrix.sync.aligned.m8n8.x4.shared.b16 {%0,%1,%2,%3}, [%4];"
                 : "=r"(r[0]), "=r"(r[1]), "=r"(r[2]), "=r"(r[3]) : "r"(addr));
}
__device__ __forceinline__ void ldm_x2(uint32_t* r, uint32_t addr) {
    asm volatile("ldmatrix.sync.aligned.m8n8.x2.shared.b16 {%0,%1}, [%2];"
                 : "=r"(r[0]), "=r"(r[1]) : "r"(addr));
}
__device__ __forceinline__ void mma_bf16(float* c, const uint32_t* a,
                                         const uint32_t* b) {
    asm volatile(
        "mma.sync.aligned.m16n8k16.row.col.f32.bf16.bf16.f32 "
        "{%0,%1,%2,%3}, {%4,%5,%6,%7}, {%8,%9}, {%0,%1,%2,%3};"
        : "+f"(c[0]), "+f"(c[1]), "+f"(c[2]), "+f"(c[3])
        : "r"(a[0]), "r"(a[1]), "r"(a[2]), "r"(a[3]), "r"(b[0]), "r"(b[1]));
}

// ===================== SMEM layout (padded rows, 144 B) =====================
#define ROWB    144                 // 72 bf16 per row (64 data + 8 pad)
#define SM_AHI  0                   // 128 x 144 = 18432
#define SM_ALO  18432
#define SM_BHI  36864               // 160 x 144 = 23040
#define SM_BLO  59904
#define SMEM_TOTAL 82944

// ============================================================================
// Split-bf16 HMMA GEMM: out[r,0:300] = relu(A(r,:) @ W + bias (+ resid))
//   mode 0: A(r,k)= k<14 ? edge_attr[r*14+k] : x[src[r]*133+k-14]    (K=147)
//   mode 2: A(r,k)= k<133? x[r*133+k]        : m_v[r*300+k-133]      (K=433)
//   mode 3: A(r,k)= inc[src[r]*300+k] - h[rev[r]*300+k]              (K=300)
// D = Ahi@Bhi + Ahi@Blo + Alo@Bhi  (fp32 accum), B[n][k]=W[k][n].
// BM=128, BN=160, BK=64; 512 threads = 16 warps (4M x 4N), warp tile 32x40.
// ============================================================================
__global__ __launch_bounds__(512)
void mma_gemm(int mode, int rows, int K, int Kpad,
              const float* __restrict__ G0,
              const float* __restrict__ G1,
              const int*   __restrict__ gidx,
              const int*   __restrict__ gidx2,
              const __nv_bfloat16* __restrict__ Whi,
              const __nv_bfloat16* __restrict__ Wlo,
              const float* __restrict__ bias,
              const float* __restrict__ resid,
              float* __restrict__ out)
{
    extern __shared__ char smem[];
    const uint32_t sb = smem_u32(smem);
    const int tid  = threadIdx.x;
    const int wid  = tid >> 5;
    const int lane = tid & 31;
    const int warp_m = wid & 3;        // 0..3 -> rows warp_m*32
    const int warp_n = wid >> 2;       // 0..3 -> cols warp_n*40
    const int m0  = blockIdx.x * 128;
    const int n0g = blockIdx.y * 160;

    // ldmatrix per-lane base offsets
    const uint32_t aOff = (uint32_t)(warp_m * 32 + (lane & 15)) * ROWB
                        + (uint32_t)((lane >> 4) * 16);          // khalf*2B
    const uint32_t bOff = (uint32_t)(warp_n * 40 + (lane & 7)) * ROWB
                        + (uint32_t)(((lane >> 3) & 1) * 16);
    const uint32_t aHi = sb + SM_AHI + aOff, aLo = sb + SM_ALO + aOff;
    const uint32_t bHi = sb + SM_BHI + bOff, bLo = sb + SM_BLO + bOff;

    float acc[2][5][4];
#pragma unroll
    for (int i = 0; i < 2; i++)
#pragma unroll
        for (int j = 0; j < 5; j++)
#pragma unroll
            for (int q = 0; q < 4; q++) acc[i][j][q] = 0.f;

    // staging indices
    const int sr   = tid >> 2;          // 0..127 row
    const int part = tid & 3;           // 16-k segment
    const int row  = m0 + sr;

    const int nch = Kpad >> 6;
    for (int c = 0; c < nch; c++) {
        const int k0 = c * 64;

        // ---------------- stage A hi/lo (128 x 64) ----------------
        char* arowH = smem + SM_AHI + sr * ROWB + part * 32;
        char* arowL = smem + SM_ALO + sr * ROWB + part * 32;
        if (mode == 3) {
            if (row < rows) {
                int s  = gidx[row];
                int rv = gidx2[row];
                const float* P = &G0[(size_t)s  * HIDDEN + k0 + part * 16];
                const float* Q = &G1[(size_t)rv * HIDDEN + k0 + part * 16];
#pragma unroll
                for (int q = 0; q < 4; q++) {
                    int kg = k0 + part * 16 + q * 4;
                    float4 v = make_float4(0.f, 0.f, 0.f, 0.f);
                    if (kg + 4 <= K) {
                        float4 p = *(const float4*)(P + q * 4);
                        float4 z = *(const float4*)(Q + q * 4);
                        v = make_float4(p.x - z.x, p.y - z.y, p.z - z.z, p.w - z.w);
                    }
                    __nv_bfloat16 hx = __float2bfloat16(v.x);
                    __nv_bfloat16 hy = __float2bfloat16(v.y);
                    __nv_bfloat16 hz = __float2bfloat16(v.z);
                    __nv_bfloat16 hw = __float2bfloat16(v.w);
                    __nv_bfloat162 h01; h01.x = hx; h01.y = hy;
                    __nv_bfloat162 h23; h23.x = hz; h23.y = hw;
                    __nv_bfloat162 l01;
                    l01.x = __float2bfloat16(v.x - __bfloat162float(hx));
                    l01.y = __float2bfloat16(v.y - __bfloat162float(hy));
                    __nv_bfloat162 l23;
                    l23.x = __float2bfloat16(v.z - __bfloat162float(hz));
                    l23.y = __float2bfloat16(v.w - __bfloat162float(hw));
                    *(__nv_bfloat162*)(arowH + q * 8)     = h01;
                    *(__nv_bfloat162*)(arowH + q * 8 + 4) = h23;
                    *(__nv_bfloat162*)(arowL + q * 8)     = l01;
                    *(__nv_bfloat162*)(arowL + q * 8 + 4) = l23;
                }
            } else {
#pragma unroll
                for (int q = 0; q < 4; q++) {
                    *(uint2*)(arowH + q * 8) = make_uint2(0u, 0u);
                    *(uint2*)(arowL + q * 8) = make_uint2(0u, 0u);
                }
            }
        } else {
            int s = 0;
            if (mode == 0 && row < rows) s = gidx[row];
#pragma unroll 4
            for (int q = 0; q < 16; q++) {
                int kg = k0 + part * 16 + q;
                float v = 0.f;
                if (row < rows) {
                    if (mode == 0) {
                        if (kg < BOND_DIM)  v = G0[(size_t)row * BOND_DIM + kg];
                        else if (kg < K)    v = G1[(size_t)s * ATOM_DIM + (kg - BOND_DIM)];
                    } else { // mode 2
                        if (kg < ATOM_DIM)  v = G0[(size_t)row * ATOM_DIM + kg];
                        else if (kg < K)    v = G1[(size_t)row * HIDDEN + (kg - ATOM_DIM)];
                    }
                }
                __nv_bfloat16 h = __float2bfloat16(v);
                *(__nv_bfloat16*)(arowH + q * 2) = h;
                *(__nv_bfloat16*)(arowL + q * 2) =
                    __float2bfloat16(v - __bfloat162float(h));
            }
        }

        // ---------------- stage B hi/lo (160 x 64): uint4 copies ----------
        for (int u = tid; u < 1280; u += 512) {
            int n = u >> 3, q = u & 7;
            char* dst = smem + n * ROWB + q * 16;
            size_t gi = (size_t)(n0g + n) * Kpad + k0 + q * 8;
            *(uint4*)(dst + SM_BHI) = *(const uint4*)&Whi[gi];
            *(uint4*)(dst + SM_BLO) = *(const uint4*)&Wlo[gi];
        }
        __syncthreads();

        // ---------------- mainloop: 4 k16 steps ----------------
#pragma unroll 1
        for (int ks = 0; ks < 4; ks++) {
            const uint32_t ko = (uint32_t)ks * 32;
            uint32_t ah0[4], ah1[4], al0[4], al1[4];
            ldm_x4(ah0, aHi + ko);
            ldm_x4(ah1, aHi + 16 * ROWB + ko);
            ldm_x4(al0, aLo + ko);
            ldm_x4(al1, aLo + 16 * ROWB + ko);
#pragma unroll
            for (int nf = 0; nf < 5; nf++) {
                uint32_t bh[2], bl[2];
                ldm_x2(bh, bHi + nf * (8 * ROWB) + ko);
                ldm_x2(bl, bLo + nf * (8 * ROWB) + ko);
                mma_bf16(acc[0][nf], ah0, bh);
                mma_bf16(acc[0][nf], ah0, bl);
                mma_bf16(acc[0][nf], al0, bh);
                mma_bf16(acc[1][nf], ah1, bh);
                mma_bf16(acc[1][nf], ah1, bl);
                mma_bf16(acc[1][nf], al1, bh);
            }
        }
        __syncthreads();
    }

    // ---------------- epilogue: bias (+resid) + relu ----------------
    const int group = lane >> 2, tig = lane & 3;
#pragma unroll
    for (int mf = 0; mf < 2; mf++) {
#pragma unroll
        for (int nf = 0; nf < 5; nf++) {
            int col = n0g + warp_n * 40 + nf * 8 + tig * 2;
            if (col >= HIDDEN) continue;
            float2 bv = *(const float2*)&bias[col];
#pragma unroll
            for (int half = 0; half < 2; half++) {
                int r = m0 + warp_m * 32 + mf * 16 + group + half * 8;
                if (r >= rows) continue;
                float vx = acc[mf][nf][half * 2 + 0] + bv.x;
                float vy = acc[mf][nf][half * 2 + 1] + bv.y;
                if (resid) {
                    float2 rz = *(const float2*)&resid[(size_t)r * HIDDEN + col];
                    vx += rz.x; vy += rz.y;
                }
                float2 o;
                o.x = vx > 0.f ? vx : 0.f;
                o.y = vy > 0.f ? vy : 0.f;
                *(float2*)&out[(size_t)r * HIDDEN + col] = o;
            }
        }
    }
}

// ---------------------------------------------------------------------------
// W pre-split: hi/lo bf16, transposed+padded to [NPAD][Kpad]
// ---------------------------------------------------------------------------
__global__ void split_w(const float* __restrict__ W, int K, int Kpad,
                        __nv_bfloat16* __restrict__ hi,
                        __nv_bfloat16* __restrict__ lo)
{
    int idx = blockIdx.x * blockDim.x + threadIdx.x;
    if (idx >= NPAD * Kpad) return;
    int n = idx / Kpad, k = idx % Kpad;
    float v = (n < HIDDEN && k < K) ? W[(size_t)k * HIDDEN + n] : 0.f;
    __nv_bfloat16 h = __float2bfloat16(v);
    hi[idx] = h;
    lo[idx] = __float2bfloat16(v - __bfloat162float(h));
}

// ---------------------------------------------------------------------------
__global__ void scatter_add(const float* __restrict__ h,
                            const int*   __restrict__ idx,
                            float* __restrict__ acc, int rows)
{
    int gid = blockIdx.x * blockDim.x + threadIdx.x;
    if (gid >= rows * 75) return;
    int e = gid / 75;
    int q = gid % 75;
    float4 v = ((const float4*)h)[(size_t)e * 75 + q];
    int d = idx[e];
    float* p = acc + (size_t)d * HIDDEN + q * 4;
    atomicAdd(p + 0, v.x);
    atomicAdd(p + 1, v.y);
    atomicAdd(p + 2, v.z);
    atomicAdd(p + 3, v.w);
}

__global__ void init_out(float* __restrict__ out, const float* __restrict__ feat)
{
    int gid = blockIdx.x * blockDim.x + threadIdx.x;
    if (gid >= N_MOL * OUT_COLS) return;
    int mol = gid / OUT_COLS;
    int c   = gid % OUT_COLS;
    out[gid] = (c < HIDDEN) ? 0.f : feat[mol * FEAT_DIM + (c - HIDDEN)];
}

__global__ void readout(const float* __restrict__ hv,
                        const int* __restrict__ mol_id,
                        float* __restrict__ out)
{
    int gid = blockIdx.x * blockDim.x + threadIdx.x;
    if (gid >= N_ATOMS * 75) return;
    int v = gid / 75;
    int q = gid % 75;
    float4 x = ((const float4*)hv)[(size_t)v * 75 + q];
    int mol = mol_id[v];
    float* p = out + (size_t)mol * OUT_COLS + q * 4;
    atomicAdd(p + 0, x.x);
    atomicAdd(p + 1, x.y);
    atomicAdd(p + 2, x.z);
    atomicAdd(p + 3, x.w);
}

// ---------------------------------------------------------------------------
extern "C" void kernel_launch(void* const* d_in, const int* in_sizes, int n_in,
                              void* d_out, int out_size)
{
    const float* x         = (const float*)d_in[0];
    const float* edge_attr = (const float*)d_in[1];
    const int*   edge_src  = (const int*)  d_in[2];
    const int*   edge_dst  = (const int*)  d_in[3];
    const int*   b2rev     = (const int*)  d_in[4];
    const int*   mol_id    = (const int*)  d_in[5];
    const float* features  = (const float*)d_in[6];
    const float* Wi        = (const float*)d_in[7];
    const float* bi        = (const float*)d_in[8];
    const float* Wm        = (const float*)d_in[9];
    const float* bm        = (const float*)d_in[10];
    const float* Wa        = (const float*)d_in[11];
    const float* ba        = (const float*)d_in[12];
    float* out = (float*)d_out;

    float *h0, *hA, *hB, *inc;
    cudaGetSymbolAddress((void**)&h0,  g_h0);
    cudaGetSymbolAddress((void**)&hA,  g_hA);
    cudaGetSymbolAddress((void**)&hB,  g_hB);
    cudaGetSymbolAddress((void**)&inc, g_inc);
    __nv_bfloat16 *wi_h, *wi_l, *wm_h, *wm_l, *wa_h, *wa_l;
    cudaGetSymbolAddress((void**)&wi_h, g_Wi_hi);
    cudaGetSymbolAddress((void**)&wi_l, g_Wi_lo);
    cudaGetSymbolAddress((void**)&wm_h, g_Wm_hi);
    cudaGetSymbolAddress((void**)&wm_l, g_Wm_lo);
    cudaGetSymbolAddress((void**)&wa_h, g_Wa_hi);
    cudaGetSymbolAddress((void**)&wa_l, g_Wa_lo);

    cudaFuncSetAttribute(mma_gemm, cudaFuncAttributeMaxDynamicSharedMemorySize,
                         SMEM_TOTAL);

    dim3 blk(256);
    dim3 mblk(512);
    dim3 gridE((NE + 127) / 128, 2);
    dim3 gridV((N_ATOMS + 127) / 128, 2);
    int scatE = (NE * 75 + 255) / 256;
    int scatV = (N_ATOMS * 75 + 255) / 256;

    // pre-split weights
    split_w<<<(NPAD * KPAD_I + 255) / 256, blk>>>(Wi, BOND_DIM + ATOM_DIM, KPAD_I, wi_h, wi_l);
    split_w<<<(NPAD * KPAD_M + 255) / 256, blk>>>(Wm, HIDDEN, KPAD_M, wm_h, wm_l);
    split_w<<<(NPAD * KPAD_A + 255) / 256, blk>>>(Wa, ATOM_DIM + HIDDEN, KPAD_A, wa_h, wa_l);

    // h0 = relu([edge_attr, x[src]] @ Wi + bi)
    mma_gemm<<<gridE, mblk, SMEM_TOTAL>>>(0, NE, BOND_DIM + ATOM_DIM, KPAD_I,
                                          edge_attr, x, edge_src, nullptr,
                                          wi_h, wi_l, bi, nullptr, h0);

    const float* hin = h0;
    float* houts[3] = { hA, hB, hA };
    for (int it = 0; it < DEPTH; it++) {
        float* hout = houts[it];
        cudaMemsetAsync(inc, 0, (size_t)N_ATOMS * HIDDEN * sizeof(float));
        scatter_add<<<scatE, blk>>>(hin, edge_dst, inc, NE);
        mma_gemm<<<gridE, mblk, SMEM_TOTAL>>>(3, NE, HIDDEN, KPAD_M,
                                              inc, hin, edge_src, b2rev,
                                              wm_h, wm_l, bm, h0, hout);
        hin = hout;
    }

    // m_v = segment_sum(h over edge_src)
    cudaMemsetAsync(inc, 0, (size_t)N_ATOMS * HIDDEN * sizeof(float));
    scatter_add<<<scatE, blk>>>(hin, edge_src, inc, NE);

    // h_v = relu([x, m_v] @ Wa + ba)
    mma_gemm<<<gridV, mblk, SMEM_TOTAL>>>(2, N_ATOMS, ATOM_DIM + HIDDEN, KPAD_A,
                                          x, inc, nullptr, nullptr,
                                          wa_h, wa_l, ba, nullptr, hB);

    // output: zeros | features, then molecule-sum readout
    init_out<<<(N_MOL * OUT_COLS + 255) / 256, blk>>>(out, features);
    readout<<<scatV, blk>>>(hB, mol_id, out);
}

// round 9
// speedup vs baseline: 2.5022x; 1.0013x over previous
#include <cuda_runtime.h>
#include <cuda_bf16.h>
#include <cstdint>

#define N_ATOMS 50000
#define N_BONDS 100000
#define NE      (2 * N_BONDS)       // 200000 directed edges
#define HIDDEN  300
#define ATOM_DIM 133
#define BOND_DIM 14
#define N_MOL   2048
#define FEAT_DIM 200
#define DEPTH   3
#define OUT_COLS (HIDDEN + FEAT_DIM)  // 500

#define NPAD    320                 // padded N (2 x 160)
#define KPAD_I  192                 // mode 0: K=147
#define KPAD_M  320                 // mode 3: K=300
#define KPAD_A  448                 // mode 2: K=433

// ---------------- scratch (device globals; no allocation allowed) ----------
__device__ float g_h0 [(size_t)NE * HIDDEN];
__device__ float g_hA [(size_t)NE * HIDDEN];
__device__ float g_hB [(size_t)NE * HIDDEN];
__device__ float g_inc[(size_t)N_ATOMS * HIDDEN];
// pre-split weights, layout [NPAD][Kpad] bf16 (B[n][k] = W[k][n]), zero-padded
__device__ __nv_bfloat16 g_Wi_hi[NPAD * KPAD_I];
__device__ __nv_bfloat16 g_Wi_lo[NPAD * KPAD_I];
__device__ __nv_bfloat16 g_Wm_hi[NPAD * KPAD_M];
__device__ __nv_bfloat16 g_Wm_lo[NPAD * KPAD_M];
__device__ __nv_bfloat16 g_Wa_hi[NPAD * KPAD_A];
__device__ __nv_bfloat16 g_Wa_lo[NPAD * KPAD_A];

// ============================ PTX helpers (sm_80+) ==========================
__device__ __forceinline__ uint32_t smem_u32(const void* p) {
    uint32_t a;
    asm("{ .reg .u64 t; cvta.to.shared.u64 t, %1; cvt.u32.u64 %0, t; }"
        : "=r"(a) : "l"(p));
    return a;
}
__device__ __forceinline__ void ldm_x4(uint32_t* r, uint32_t addr) {
    asm volatile("ldmatrix.sync.aligned.m8n8.x4.shared.b16 {%0,%1,%2,%3}, [%4];"
                 : "=r"(r[0]), "=r"(r[1]), "=r"(r[2]), "=r"(r[3]) : "r"(addr));
}
__device__ __forceinline__ void ldm_x2(uint32_t* r, uint32_t addr) {
    asm volatile("ldmatrix.sync.aligned.m8n8.x2.shared.b16 {%0,%1}, [%2];"
                 : "=r"(r[0]), "=r"(r[1]) : "r"(addr));
}
__device__ __forceinline__ void mma_bf16(float* c, const uint32_t* a,
                                         const uint32_t* b) {
    asm volatile(
        "mma.sync.aligned.m16n8k16.row.col.f32.bf16.bf16.f32 "
        "{%0,%1,%2,%3}, {%4,%5,%6,%7}, {%8,%9}, {%0,%1,%2,%3};"
        : "+f"(c[0]), "+f"(c[1]), "+f"(c[2]), "+f"(c[3])
        : "r"(a[0]), "r"(a[1]), "r"(a[2]), "r"(a[3]), "r"(b[0]), "r"(b[1]));
}

// ===================== SMEM layout (padded rows, 144 B) =====================
#define ROWB    144                 // 72 bf16 per row (64 data + 8 pad)
#define SM_AHI  0                   // 128 x 144 = 18432
#define SM_ALO  18432
#define SM_BHI  36864               // 160 x 144 = 23040
#define SM_BLO  59904
#define SMEM_TOTAL 82944

// ============================================================================
// Split-bf16 HMMA GEMM: out[r,0:300] = relu(A(r,:) @ W + bias (+ resid))
//   mode 0: A(r,k)= k<14 ? edge_attr[r*14+k] : x[src[r]*133+k-14]    (K=147)
//   mode 2: A(r,k)= k<133? x[r*133+k]        : m_v[r*300+k-133]      (K=433)
//   mode 3: A(r,k)= inc[src[r]*300+k] - h[rev[r]*300+k]              (K=300)
// D = Ahi@Bhi + Ahi@Blo + Alo@Bhi  (fp32 accum), B[n][k]=W[k][n].
// BM=128, BN=160, BK=64; 512 threads = 16 warps (4M x 4N), warp tile 32x40.
// ============================================================================
__global__ __launch_bounds__(512)
void mma_gemm(int mode, int rows, int K, int Kpad,
              const float* __restrict__ G0,
              const float* __restrict__ G1,
              const int*   __restrict__ gidx,
              const int*   __restrict__ gidx2,
              const __nv_bfloat16* __restrict__ Whi,
              const __nv_bfloat16* __restrict__ Wlo,
              const float* __restrict__ bias,
              const float* __restrict__ resid,
              float* __restrict__ out)
{
    extern __shared__ char smem[];
    const uint32_t sb = smem_u32(smem);
    const int tid  = threadIdx.x;
    const int wid  = tid >> 5;
    const int lane = tid & 31;
    const int warp_m = wid & 3;        // 0..3 -> rows warp_m*32
    const int warp_n = wid >> 2;       // 0..3 -> cols warp_n*40
    const int m0  = blockIdx.x * 128;
    const int n0g = blockIdx.y * 160;

    // ldmatrix per-lane base offsets
    const uint32_t aOff = (uint32_t)(warp_m * 32 + (lane & 15)) * ROWB
                        + (uint32_t)((lane >> 4) * 16);          // khalf*2B
    const uint32_t bOff = (uint32_t)(warp_n * 40 + (lane & 7)) * ROWB
                        + (uint32_t)(((lane >> 3) & 1) * 16);
    const uint32_t aHi = sb + SM_AHI + aOff, aLo = sb + SM_ALO + aOff;
    const uint32_t bHi = sb + SM_BHI + bOff, bLo = sb + SM_BLO + bOff;

    float acc[2][5][4];
#pragma unroll
    for (int i = 0; i < 2; i++)
#pragma unroll
        for (int j = 0; j < 5; j++)
#pragma unroll
            for (int q = 0; q < 4; q++) acc[i][j][q] = 0.f;

    // staging indices
    const int sr   = tid >> 2;          // 0..127 row
    const int part = tid & 3;           // 16-k segment
    const int row  = m0 + sr;

    const int nch = Kpad >> 6;
    for (int c = 0; c < nch; c++) {
        const int k0 = c * 64;

        // ---------------- stage A hi/lo (128 x 64) ----------------
        char* arowH = smem + SM_AHI + sr * ROWB + part * 32;
        char* arowL = smem + SM_ALO + sr * ROWB + part * 32;
        if (mode == 3) {
            if (row < rows) {
                int s  = gidx[row];
                int rv = gidx2[row];
                const float* P = &G0[(size_t)s  * HIDDEN + k0 + part * 16];
                const float* Q = &G1[(size_t)rv * HIDDEN + k0 + part * 16];
#pragma unroll
                for (int q = 0; q < 4; q++) {
                    int kg = k0 + part * 16 + q * 4;
                    float4 v = make_float4(0.f, 0.f, 0.f, 0.f);
                    if (kg + 4 <= K) {
                        float4 p = *(const float4*)(P + q * 4);
                        float4 z = *(const float4*)(Q + q * 4);
                        v = make_float4(p.x - z.x, p.y - z.y, p.z - z.z, p.w - z.w);
                    }
                    __nv_bfloat16 hx = __float2bfloat16(v.x);
                    __nv_bfloat16 hy = __float2bfloat16(v.y);
                    __nv_bfloat16 hz = __float2bfloat16(v.z);
                    __nv_bfloat16 hw = __float2bfloat16(v.w);
                    __nv_bfloat162 h01; h01.x = hx; h01.y = hy;
                    __nv_bfloat162 h23; h23.x = hz; h23.y = hw;
                    __nv_bfloat162 l01;
                    l01.x = __float2bfloat16(v.x - __bfloat162float(hx));
                    l01.y = __float2bfloat16(v.y - __bfloat162float(hy));
                    __nv_bfloat162 l23;
                    l23.x = __float2bfloat16(v.z - __bfloat162float(hz));
                    l23.y = __float2bfloat16(v.w - __bfloat162float(hw));
                    *(__nv_bfloat162*)(arowH + q * 8)     = h01;
                    *(__nv_bfloat162*)(arowH + q * 8 + 4) = h23;
                    *(__nv_bfloat162*)(arowL + q * 8)     = l01;
                    *(__nv_bfloat162*)(arowL + q * 8 + 4) = l23;
                }
            } else {
#pragma unroll
                for (int q = 0; q < 4; q++) {
                    *(uint2*)(arowH + q * 8) = make_uint2(0u, 0u);
                    *(uint2*)(arowL + q * 8) = make_uint2(0u, 0u);
                }
            }
        } else {
            int s = 0;
            if (mode == 0 && row < rows) s = gidx[row];
#pragma unroll 4
            for (int q = 0; q < 16; q++) {
                int kg = k0 + part * 16 + q;
                float v = 0.f;
                if (row < rows) {
                    if (mode == 0) {
                        if (kg < BOND_DIM)  v = G0[(size_t)row * BOND_DIM + kg];
                        else if (kg < K)    v = G1[(size_t)s * ATOM_DIM + (kg - BOND_DIM)];
                    } else { // mode 2
                        if (kg < ATOM_DIM)  v = G0[(size_t)row * ATOM_DIM + kg];
                        else if (kg < K)    v = G1[(size_t)row * HIDDEN + (kg - ATOM_DIM)];
                    }
                }
                __nv_bfloat16 h = __float2bfloat16(v);
                *(__nv_bfloat16*)(arowH + q * 2) = h;
                *(__nv_bfloat16*)(arowL + q * 2) =
                    __float2bfloat16(v - __bfloat162float(h));
            }
        }

        // ---------------- stage B hi/lo (160 x 64): uint4 copies ----------
        for (int u = tid; u < 1280; u += 512) {
            int n = u >> 3, q = u & 7;
            char* dst = smem + n * ROWB + q * 16;
            size_t gi = (size_t)(n0g + n) * Kpad + k0 + q * 8;
            *(uint4*)(dst + SM_BHI) = *(const uint4*)&Whi[gi];
            *(uint4*)(dst + SM_BLO) = *(const uint4*)&Wlo[gi];
        }
        __syncthreads();

        // ---------------- mainloop: 4 k16 steps ----------------
#pragma unroll 1
        for (int ks = 0; ks < 4; ks++) {
            const uint32_t ko = (uint32_t)ks * 32;
            uint32_t ah0[4], ah1[4], al0[4], al1[4];
            ldm_x4(ah0, aHi + ko);
            ldm_x4(ah1, aHi + 16 * ROWB + ko);
            ldm_x4(al0, aLo + ko);
            ldm_x4(al1, aLo + 16 * ROWB + ko);
#pragma unroll
            for (int nf = 0; nf < 5; nf++) {
                uint32_t bh[2], bl[2];
                ldm_x2(bh, bHi + nf * (8 * ROWB) + ko);
                ldm_x2(bl, bLo + nf * (8 * ROWB) + ko);
                mma_bf16(acc[0][nf], ah0, bh);
                mma_bf16(acc[0][nf], ah0, bl);
                mma_bf16(acc[0][nf], al0, bh);
                mma_bf16(acc[1][nf], ah1, bh);
                mma_bf16(acc[1][nf], ah1, bl);
                mma_bf16(acc[1][nf], al1, bh);
            }
        }
        __syncthreads();
    }

    // ---------------- epilogue: bias (+resid) + relu ----------------
    const int group = lane >> 2, tig = lane & 3;
#pragma unroll
    for (int mf = 0; mf < 2; mf++) {
#pragma unroll
        for (int nf = 0; nf < 5; nf++) {
            int col = n0g + warp_n * 40 + nf * 8 + tig * 2;
            if (col >= HIDDEN) continue;
            float2 bv = *(const float2*)&bias[col];
#pragma unroll
            for (int half = 0; half < 2; half++) {
                int r = m0 + warp_m * 32 + mf * 16 + group + half * 8;
                if (r >= rows) continue;
                float vx = acc[mf][nf][half * 2 + 0] + bv.x;
                float vy = acc[mf][nf][half * 2 + 1] + bv.y;
                if (resid) {
                    float2 rz = *(const float2*)&resid[(size_t)r * HIDDEN + col];
                    vx += rz.x; vy += rz.y;
                }
                float2 o;
                o.x = vx > 0.f ? vx : 0.f;
                o.y = vy > 0.f ? vy : 0.f;
                *(float2*)&out[(size_t)r * HIDDEN + col] = o;
            }
        }
    }
}

// ---------------------------------------------------------------------------
// W pre-split: hi/lo bf16, transposed+padded to [NPAD][Kpad]
// ---------------------------------------------------------------------------
__global__ void split_w(const float* __restrict__ W, int K, int Kpad,
                        __nv_bfloat16* __restrict__ hi,
                        __nv_bfloat16* __restrict__ lo)
{
    int idx = blockIdx.x * blockDim.x + threadIdx.x;
    if (idx >= NPAD * Kpad) return;
    int n = idx / Kpad, k = idx % Kpad;
    float v = (n < HIDDEN && k < K) ? W[(size_t)k * HIDDEN + n] : 0.f;
    __nv_bfloat16 h = __float2bfloat16(v);
    hi[idx] = h;
    lo[idx] = __float2bfloat16(v - __bfloat162float(h));
}

// ---------------------------------------------------------------------------
__global__ void scatter_add(const float* __restrict__ h,
                            const int*   __restrict__ idx,
                            float* __restrict__ acc, int rows)
{
    int gid = blockIdx.x * blockDim.x + threadIdx.x;
    if (gid >= rows * 75) return;
    int e = gid / 75;
    int q = gid % 75;
    float4 v = ((const float4*)h)[(size_t)e * 75 + q];
    int d = idx[e];
    float* p = acc + (size_t)d * HIDDEN + q * 4;
    atomicAdd(p + 0, v.x);
    atomicAdd(p + 1, v.y);
    atomicAdd(p + 2, v.z);
    atomicAdd(p + 3, v.w);
}

__global__ void init_out(float* __restrict__ out, const float* __restrict__ feat)
{
    int gid = blockIdx.x * blockDim.x + threadIdx.x;
    if (gid >= N_MOL * OUT_COLS) return;
    int mol = gid / OUT_COLS;
    int c   = gid % OUT_COLS;
    out[gid] = (c < HIDDEN) ? 0.f : feat[mol * FEAT_DIM + (c - HIDDEN)];
}

__global__ void readout(const float* __restrict__ hv,
                        const int* __restrict__ mol_id,
                        float* __restrict__ out)
{
    int gid = blockIdx.x * blockDim.x + threadIdx.x;
    if (gid >= N_ATOMS * 75) return;
    int v = gid / 75;
    int q = gid % 75;
    float4 x = ((const float4*)hv)[(size_t)v * 75 + q];
    int mol = mol_id[v];
    float* p = out + (size_t)mol * OUT_COLS + q * 4;
    atomicAdd(p + 0, x.x);
    atomicAdd(p + 1, x.y);
    atomicAdd(p + 2, x.z);
    atomicAdd(p + 3, x.w);
}

// ---------------------------------------------------------------------------
extern "C" void kernel_launch(void* const* d_in, const int* in_sizes, int n_in,
                              void* d_out, int out_size)
{
    const float* x         = (const float*)d_in[0];
    const float* edge_attr = (const float*)d_in[1];
    const int*   edge_src  = (const int*)  d_in[2];
    const int*   edge_dst  = (const int*)  d_in[3];
    const int*   b2rev     = (const int*)  d_in[4];
    const int*   mol_id    = (const int*)  d_in[5];
    const float* features  = (const float*)d_in[6];
    const float* Wi        = (const float*)d_in[7];
    const float* bi        = (const float*)d_in[8];
    const float* Wm        = (const float*)d_in[9];
    const float* bm        = (const float*)d_in[10];
    const float* Wa        = (const float*)d_in[11];
    const float* ba        = (const float*)d_in[12];
    float* out = (float*)d_out;

    float *h0, *hA, *hB, *inc;
    cudaGetSymbolAddress((void**)&h0,  g_h0);
    cudaGetSymbolAddress((void**)&hA,  g_hA);
    cudaGetSymbolAddress((void**)&hB,  g_hB);
    cudaGetSymbolAddress((void**)&inc, g_inc);
    __nv_bfloat16 *wi_h, *wi_l, *wm_h, *wm_l, *wa_h, *wa_l;
    cudaGetSymbolAddress((void**)&wi_h, g_Wi_hi);
    cudaGetSymbolAddress((void**)&wi_l, g_Wi_lo);
    cudaGetSymbolAddress((void**)&wm_h, g_Wm_hi);
    cudaGetSymbolAddress((void**)&wm_l, g_Wm_lo);
    cudaGetSymbolAddress((void**)&wa_h, g_Wa_hi);
    cudaGetSymbolAddress((void**)&wa_l, g_Wa_lo);

    cudaFuncSetAttribute(mma_gemm, cudaFuncAttributeMaxDynamicSharedMemorySize,
                         SMEM_TOTAL);

    dim3 blk(256);
    dim3 mblk(512);
    dim3 gridE((NE + 127) / 128, 2);
    dim3 gridV((N_ATOMS + 127) / 128, 2);
    int scatE = (NE * 75 + 255) / 256;
    int scatV = (N_ATOMS * 75 + 255) / 256;

    // pre-split weights
    split_w<<<(NPAD * KPAD_I + 255) / 256, blk>>>(Wi, BOND_DIM + ATOM_DIM, KPAD_I, wi_h, wi_l);
    split_w<<<(NPAD * KPAD_M + 255) / 256, blk>>>(Wm, HIDDEN, KPAD_M, wm_h, wm_l);
    split_w<<<(NPAD * KPAD_A + 255) / 256, blk>>>(Wa, ATOM_DIM + HIDDEN, KPAD_A, wa_h, wa_l);

    // h0 = relu([edge_attr, x[src]] @ Wi + bi)
    mma_gemm<<<gridE, mblk, SMEM_TOTAL>>>(0, NE, BOND_DIM + ATOM_DIM, KPAD_I,
                                          edge_attr, x, edge_src, nullptr,
                                          wi_h, wi_l, bi, nullptr, h0);

    const float* hin = h0;
    float* houts[3] = { hA, hB, hA };
    for (int it = 0; it < DEPTH; it++) {
        float* hout = houts[it];
        cudaMemsetAsync(inc, 0, (size_t)N_ATOMS * HIDDEN * sizeof(float));
        scatter_add<<<scatE, blk>>>(hin, edge_dst, inc, NE);
        mma_gemm<<<gridE, mblk, SMEM_TOTAL>>>(3, NE, HIDDEN, KPAD_M,
                                              inc, hin, edge_src, b2rev,
                                              wm_h, wm_l, bm, h0, hout);
        hin = hout;
    }

    // m_v = segment_sum(h over edge_src)
    cudaMemsetAsync(inc, 0, (size_t)N_ATOMS * HIDDEN * sizeof(float));
    scatter_add<<<scatE, blk>>>(hin, edge_src, inc, NE);

    // h_v = relu([x, m_v] @ Wa + ba)
    mma_gemm<<<gridV, mblk, SMEM_TOTAL>>>(2, N_ATOMS, ATOM_DIM + HIDDEN, KPAD_A,
                                          x, inc, nullptr, nullptr,
                                          wa_h, wa_l, ba, nullptr, hB);

    // output: zeros | features, then molecule-sum readout
    init_out<<<(N_MOL * OUT_COLS + 255) / 256, blk>>>(out, features);
    readout<<<scatV, blk>>>(hB, mol_id, out);
}